// round 3
// baseline (speedup 1.0000x reference)
#include <cuda_runtime.h>

// Problem constants (fixed by the reference): B=2048, F=40, E=64, I=780
#define FDIM   40
#define EDIM   64
#define NPAIR  780          // F*(F-1)/2
#define BT     8            // batches per block
#define E4     (EDIM / 4)   // 16 float4 chunks per row
#define ROWSTRIDE 68        // smem floats per field row (64 + 4 pad)
#define BSTRIDE   (FDIM * ROWSTRIDE)   // 2720 floats per batch in smem
#define NGROUP 20           // field groups of 2
#define NFULL  190          // C(20,2) full 2x2 tiles
#define NTILE  210          // 190 full + 20 diagonal singleton pairs

// Scratch for the kernel-sum (sum over axis 0 of the (E, I, E) kernel tensor)
__device__ float g_ksum[NPAIR * EDIM];

// ---------------------------------------------------------------------------
// Kernel 1: ksum[p][e] = sum_k kernel[k][p][e]   (kernel is (E, I, E) row-major)
// ---------------------------------------------------------------------------
__global__ void ksum_kernel(const float* __restrict__ kern)
{
    const int n4 = NPAIR * EDIM / 4;          // 12480 float4 elements
    int idx4 = blockIdx.x * blockDim.x + threadIdx.x;
    if (idx4 >= n4) return;

    const float4* k4 = reinterpret_cast<const float4*>(kern);
    float4 s = make_float4(0.f, 0.f, 0.f, 0.f);
    #pragma unroll 8
    for (int k = 0; k < EDIM; ++k) {
        float4 v = k4[(size_t)k * n4 + idx4];
        s.x += v.x; s.y += v.y; s.z += v.z; s.w += v.w;
    }
    reinterpret_cast<float4*>(g_ksum)[idx4] = s;
}

// dot4 accumulate: acc += sum_c wv.c * xi.c * xj.c
__device__ __forceinline__ void dot4(float& acc, const float4 wv,
                                     const float4 xi, const float4 xj)
{
    acc = fmaf(wv.x * xi.x, xj.x, acc);
    acc = fmaf(wv.y * xi.y, xj.y, acc);
    acc = fmaf(wv.z * xi.z, xj.z, acc);
    acc = fmaf(wv.w * xi.w, xj.w, acc);
}

// ---------------------------------------------------------------------------
// Kernel 2: out[b][p] = sum_e A[b][i_p][e] * ksum[p][e] * A[b][j_p][e]
// One block = BT batches (staged in smem). Threads own 2x2 field tiles:
// 4 pairs computed from 4 smem row-loads (2x LDS reduction vs per-pair).
// ---------------------------------------------------------------------------
__global__ void __launch_bounds__(256, 2) interact_kernel(
    const float* __restrict__ A,   // (B, F, E) row-major
    float*       __restrict__ out) // (B, NPAIR) row-major
{
    extern __shared__ float smem[];
    float* sA = smem;                                        // BT * BSTRIDE floats
    unsigned char*  s_i0 = (unsigned char*)(smem + BT * BSTRIDE);
    unsigned char*  s_j0 = s_i0 + 256;
    unsigned short* s_p  = (unsigned short*)(s_j0 + 256);

    const int tid = threadIdx.x;
    const int b0  = blockIdx.x * BT;

    // ---- build tile table: 190 full 2x2 tiles + 20 diagonal pairs ----
    for (int t = tid; t < NTILE; t += 256) {
        int i0, j0;
        if (t < NFULL) {
            int ig = 0, cum = 0;
            while (cum + (NGROUP - 1 - ig) <= t) { cum += NGROUP - 1 - ig; ++ig; }
            int jg = ig + 1 + (t - cum);
            i0 = 2 * ig; j0 = 2 * jg;
        } else {
            int g = t - NFULL;
            i0 = 2 * g; j0 = 2 * g + 1;
        }
        s_i0[t] = (unsigned char)i0;
        s_j0[t] = (unsigned char)j0;
        // pair index of (i0, j0):  offset(i0) + j0 - i0 - 1
        s_p[t] = (unsigned short)(i0 * (FDIM - 1) - i0 * (i0 - 1) / 2 + j0 - i0 - 1);
    }

    // ---- stage BT batches of A into padded smem (float4 loads) ----
    const float4* A4 = reinterpret_cast<const float4*>(A);
    for (int v = tid; v < BT * FDIM * E4; v += 256) {
        int b  = v / (FDIM * E4);
        int r  = v % (FDIM * E4);
        int f  = r / E4;
        int e4 = r % E4;
        float4 val = A4[(size_t)(b0 + b) * (FDIM * E4) + f * E4 + e4];
        *reinterpret_cast<float4*>(&sA[b * BSTRIDE + f * ROWSTRIDE + e4 * 4]) = val;
    }
    __syncthreads();

    const int t = tid;
    if (t >= NTILE) return;

    const float4* w4 = reinterpret_cast<const float4*>(g_ksum);
    const int i0 = s_i0[t];
    const int ia = i0 * ROWSTRIDE;
    const int ja = s_j0[t] * ROWSTRIDE;
    const int p00 = s_p[t];

    if (t < NFULL) {
        // -------- full 2x2 tile: pairs (i0,j0) (i0,j1) (i1,j0) (i1,j1) --------
        const int ib = ia + ROWSTRIDE;
        const int jb = ja + ROWSTRIDE;
        const int p10 = p00 + (FDIM - 2 - i0);   // pair index of (i0+1, j0)

        const float4* wp00 = w4 + (size_t)p00 * E4;
        const float4* wp01 = wp00 + E4;
        const float4* wp10 = w4 + (size_t)p10 * E4;
        const float4* wp11 = wp10 + E4;

        float acc00[BT], acc01[BT], acc10[BT], acc11[BT];
        #pragma unroll
        for (int b = 0; b < BT; ++b) { acc00[b]=0.f; acc01[b]=0.f; acc10[b]=0.f; acc11[b]=0.f; }

        #pragma unroll 2
        for (int e4 = 0; e4 < E4; ++e4) {
            const float4 w00 = wp00[e4];
            const float4 w01 = wp01[e4];
            const float4 w10 = wp10[e4];
            const float4 w11 = wp11[e4];
            const int eo = e4 * 4;
            #pragma unroll
            for (int b = 0; b < BT; ++b) {
                const float* bb = sA + b * BSTRIDE + eo;
                const float4 xi0 = *reinterpret_cast<const float4*>(bb + ia);
                const float4 xi1 = *reinterpret_cast<const float4*>(bb + ib);
                const float4 xj0 = *reinterpret_cast<const float4*>(bb + ja);
                const float4 xj1 = *reinterpret_cast<const float4*>(bb + jb);
                dot4(acc00[b], w00, xi0, xj0);
                dot4(acc01[b], w01, xi0, xj1);
                dot4(acc10[b], w10, xi1, xj0);
                dot4(acc11[b], w11, xi1, xj1);
            }
        }

        #pragma unroll
        for (int b = 0; b < BT; ++b) {
            float* o = out + (size_t)(b0 + b) * NPAIR;
            o[p00]     = acc00[b];
            o[p00 + 1] = acc01[b];
            o[p10]     = acc10[b];
            o[p10 + 1] = acc11[b];
        }
    } else {
        // -------- diagonal singleton pair (2g, 2g+1) --------
        const float4* wp = w4 + (size_t)p00 * E4;

        float acc[BT];
        #pragma unroll
        for (int b = 0; b < BT; ++b) acc[b] = 0.f;

        #pragma unroll 2
        for (int e4 = 0; e4 < E4; ++e4) {
            const float4 wv = wp[e4];
            const int eo = e4 * 4;
            #pragma unroll
            for (int b = 0; b < BT; ++b) {
                const float* bb = sA + b * BSTRIDE + eo;
                const float4 xi = *reinterpret_cast<const float4*>(bb + ia);
                const float4 xj = *reinterpret_cast<const float4*>(bb + ja);
                dot4(acc[b], wv, xi, xj);
            }
        }

        #pragma unroll
        for (int b = 0; b < BT; ++b)
            out[(size_t)(b0 + b) * NPAIR + p00] = acc[b];
    }
}

// ---------------------------------------------------------------------------
// Launch
// ---------------------------------------------------------------------------
extern "C" void kernel_launch(void* const* d_in, const int* in_sizes, int n_in,
                              void* d_out, int out_size)
{
    const float* inputs = (const float*)d_in[0];   // (B, F, E) float32
    const float* kern   = (const float*)d_in[1];   // (E, I, E) float32
    (void)n_in; (void)out_size;

    const int B = in_sizes[0] / (FDIM * EDIM);     // 2048

    const size_t smem_bytes = (size_t)BT * BSTRIDE * sizeof(float) + 1536;
    cudaFuncSetAttribute(interact_kernel,
                         cudaFuncAttributeMaxDynamicSharedMemorySize,
                         (int)smem_bytes);

    // 1) reduce kernel tensor over axis 0
    {
        const int n4 = NPAIR * EDIM / 4;
        ksum_kernel<<<(n4 + 255) / 256, 256>>>(kern);
    }
    // 2) pairwise interactions
    interact_kernel<<<B / BT, 256, smem_bytes>>>(inputs, (float*)d_out);
}